// round 5
// baseline (speedup 1.0000x reference)
#include <cuda_runtime.h>
#include <math.h>

#define D_     1024
#define BLK    256
#define GRIDP  512
#define ROWS_  8
#define PAIRS  4          // warp-pairs per block in pass2
#define NMAX   512
#define MMAX   16384
#define EPS_   1e-5f

// ---- scratch (static device globals; no allocation) ----
__device__ float g_colpart[GRIDP * D_];
__device__ float g_gate[MMAX];
__device__ float g_mean[D_];
__device__ float g_sims[NMAX];
__device__ int   g_valid[NMAX];
__device__ float g_damp, g_qscale;   // qscale = coeff/damp
__device__ int   g_nidx;
__device__ int   g_ctr = 0;

__device__ __forceinline__ float wsum(float v) {
    v += __shfl_xor_sync(0xffffffffu, v, 16);
    v += __shfl_xor_sync(0xffffffffu, v, 8);
    v += __shfl_xor_sync(0xffffffffu, v, 4);
    v += __shfl_xor_sync(0xffffffffu, v, 2);
    v += __shfl_xor_sync(0xffffffffu, v, 1);
    return v;
}

__device__ __forceinline__ float tanh_ap(float u) {
    float r;
    asm("tanh.approx.f32 %0, %1;" : "=f"(r) : "f"(u));
    return r;
}

__device__ __forceinline__ float gelu_f(float x) {
    float u = 0.7978845608028654f * fmaf(0.044715f * x, x * x, x);
    return (0.5f * x) * (1.0f + tanh_ap(u));
}

// ---------------- pass 1: gates + y1 column partial sums ----------------
// single __syncthreads per 8-row chunk; gates computed redundantly per warp
__global__ void __launch_bounds__(BLK) k_pass1(
    const float* __restrict__ x,
    const float* __restrict__ ema_x, const float* __restrict__ ema_x2,
    const float* __restrict__ ema_y, const float* __restrict__ ema_y2,
    const float* __restrict__ p_lt_in, const float* __restrict__ p_lt_out,
    const float* __restrict__ p_la_in, const float* __restrict__ p_la_out,
    int M)
{
    const int t = threadIdx.x;
    const int c = t * 4;
    const int lane = t & 31, w = t >> 5;

    float4 ex = *(const float4*)(ema_x + c);
    float4 e2 = *(const float4*)(ema_x2 + c);
    float4 ey = *(const float4*)(ema_y + c);
    float4 f2 = *(const float4*)(ema_y2 + c);
    float4 isx, isy, nx, ny;
    isx.x = 1.0f / (sqrtf(fmaxf(e2.x - ex.x * ex.x, 0.0f)) + EPS_);
    isx.y = 1.0f / (sqrtf(fmaxf(e2.y - ex.y * ex.y, 0.0f)) + EPS_);
    isx.z = 1.0f / (sqrtf(fmaxf(e2.z - ex.z * ex.z, 0.0f)) + EPS_);
    isx.w = 1.0f / (sqrtf(fmaxf(e2.w - ex.w * ex.w, 0.0f)) + EPS_);
    isy.x = 1.0f / (sqrtf(fmaxf(f2.x - ey.x * ey.x, 0.0f)) + EPS_);
    isy.y = 1.0f / (sqrtf(fmaxf(f2.y - ey.y * ey.y, 0.0f)) + EPS_);
    isy.z = 1.0f / (sqrtf(fmaxf(f2.z - ey.z * ey.z, 0.0f)) + EPS_);
    isy.w = 1.0f / (sqrtf(fmaxf(f2.w - ey.w * ey.w, 0.0f)) + EPS_);
    nx.x = -ex.x * isx.x; nx.y = -ex.y * isx.y; nx.z = -ex.z * isx.z; nx.w = -ex.w * isx.w;
    ny.x = -ey.x * isy.x; ny.y = -ey.y * isy.y; ny.z = -ey.z * isy.z; ny.w = -ey.w * isy.w;

    const float tau_in  = expf(p_lt_in[0]);
    const float tau_out = expf(p_lt_out[0]);
    const float a_in    = 1.0f / (1.0f + expf(-p_la_in[0]));
    const float a_out   = 1.0f / (1.0f + expf(-p_la_out[0]));
    const float b_in = 1.0f - a_in, b_out = 1.0f - a_out;

    __shared__ float s_red[2][8][16];   // [parity][warp][zx0..7, zy0..7]

    float4 acc = make_float4(0.f, 0.f, 0.f, 0.f);
    const int nchunk = M / ROWS_;
    int parity = 0;

    for (int ch = blockIdx.x; ch < nchunk; ch += GRIDP, parity ^= 1) {
        const float* xp = x + (size_t)ch * (ROWS_ * D_) + c;
        float4 xv[ROWS_];
#pragma unroll
        for (int r = 0; r < ROWS_; r++)
            xv[r] = *(const float4*)(xp + r * D_);

        float4 yv[ROWS_];
        float zx[ROWS_], zy[ROWS_];
#pragma unroll
        for (int r = 0; r < ROWS_; r++) {
            float4 X = xv[r];
            float4 Y;
            Y.x = gelu_f(X.x); Y.y = gelu_f(X.y);
            Y.z = gelu_f(X.z); Y.w = gelu_f(X.w);
            yv[r] = Y;
            float d0 = fmaf(X.x, isx.x, nx.x), d1 = fmaf(X.y, isx.y, nx.y);
            float d2 = fmaf(X.z, isx.z, nx.z), d3 = fmaf(X.w, isx.w, nx.w);
            zx[r] = fmaf(d0, d0, fmaf(d1, d1, fmaf(d2, d2, d3 * d3)));
            float g0 = fmaf(Y.x, isy.x, ny.x), g1 = fmaf(Y.y, isy.y, ny.y);
            float g2 = fmaf(Y.z, isy.z, ny.z), g3 = fmaf(Y.w, isy.w, ny.w);
            zy[r] = fmaf(g0, g0, fmaf(g1, g1, fmaf(g2, g2, g3 * g3)));
        }
#pragma unroll
        for (int r = 0; r < ROWS_; r++) { zx[r] = wsum(zx[r]); zy[r] = wsum(zy[r]); }
        if (lane == 0) {
#pragma unroll
            for (int r = 0; r < ROWS_; r++) {
                s_red[parity][w][r] = zx[r];
                s_red[parity][w][8 + r] = zy[r];
            }
        }
        __syncthreads();

        // every warp redundantly reduces + computes all 8 gates
        float val = 0.f;
        const int li = lane & 15;
#pragma unroll
        for (int ww = 0; ww < 8; ww++) val += s_red[parity][ww][li];
        val *= (1.0f / D_);
        float zi = __shfl_sync(0xffffffffu, val, lane & 7);
        float zo = __shfl_sync(0xffffffffu, val, (lane & 7) + 8);
        float g = (b_in + a_in * expf(-tau_in * zi)) *
                  (b_out + a_out * expf(-tau_out * zo));
        if (w == 0 && lane < 8) g_gate[ch * ROWS_ + lane] = g;
#pragma unroll
        for (int r = 0; r < ROWS_; r++) {
            float ga = __shfl_sync(0xffffffffu, g, r);
            acc.x = fmaf(yv[r].x, ga, acc.x);
            acc.y = fmaf(yv[r].y, ga, acc.y);
            acc.z = fmaf(yv[r].z, ga, acc.z);
            acc.w = fmaf(yv[r].w, ga, acc.w);
        }
        // double-buffered s_red: no trailing barrier needed
    }
    *(float4*)(g_colpart + blockIdx.x * D_ + c) = acc;
}

// ---------------- reduce column partials -> y1_mean ---------------------
__global__ void __launch_bounds__(BLK) k_colreduce(float invM)
{
    const int t = threadIdx.x;
    const int col = blockIdx.x * 8 + (t & 7);
    const int gs = t >> 3;
    float s = 0.f;
#pragma unroll
    for (int k = 0; k < GRIDP / 32; k++) {
        int g = gs + k * 32;
        s += g_colpart[g * D_ + col];
    }
    __shared__ float sm[32][8];
    sm[gs][t & 7] = s;
    __syncthreads();
    if (t < 8) {
        float tot = 0.f;
#pragma unroll
        for (int i = 0; i < 32; i++) tot += sm[i][t];
        g_mean[blockIdx.x * 8 + t] = tot * invM;
    }
}

// ---------------- sims + fused argmax/select ----------------------------
__global__ void __launch_bounds__(128) k_sims(
    const float* __restrict__ buf, const float* __restrict__ facil,
    const float* __restrict__ p_lkb, const float* __restrict__ p_lkd,
    int N)
{
    const int n = blockIdx.x;
    const int t = threadIdx.x;
    const int lane = t & 31, w = t >> 5;
    const float4* bp = (const float4*)(buf + (size_t)n * D_);
    const float4* mp = (const float4*)g_mean;

    float dot = 0.f, b2 = 0.f, m2 = 0.f;
    int fin = 1;
#pragma unroll
    for (int k = 0; k < 2; k++) {
        float4 bv = bp[t + k * 128];
        float4 mv = mp[t + k * 128];
        dot = fmaf(bv.x, mv.x, fmaf(bv.y, mv.y, fmaf(bv.z, mv.z, fmaf(bv.w, mv.w, dot))));
        b2  = fmaf(bv.x, bv.x, fmaf(bv.y, bv.y, fmaf(bv.z, bv.z, fmaf(bv.w, bv.w, b2))));
        m2  = fmaf(mv.x, mv.x, fmaf(mv.y, mv.y, fmaf(mv.z, mv.z, fmaf(mv.w, mv.w, m2))));
        fin &= (fabsf(bv.x) <= 3.4028234e38f) & (fabsf(bv.y) <= 3.4028234e38f) &
               (fabsf(bv.z) <= 3.4028234e38f) & (fabsf(bv.w) <= 3.4028234e38f);
    }
    dot = wsum(dot); b2 = wsum(b2); m2 = wsum(m2);
    fin = __all_sync(0xffffffffu, fin);
    __shared__ float sd[4], sb[4], sm2[4];
    __shared__ int sf[4];
    if (lane == 0) { sd[w] = dot; sb[w] = b2; sm2[w] = m2; sf[w] = fin; }
    __syncthreads();
    if (t == 0) {
        float dt = sd[0] + sd[1] + sd[2] + sd[3];
        float bb = sb[0] + sb[1] + sb[2] + sb[3];
        float mm = sm2[0] + sm2[1] + sm2[2] + sm2[3];
        float bnorm = fmaxf(sqrtf(bb), 1e-12f);
        float mnorm = fmaxf(sqrtf(mm), 1e-12f);
        g_sims[n] = dt / (bnorm * mnorm);
        g_valid[n] = (sf[0] & sf[1] & sf[2] & sf[3]) && (sqrtf(bb) >= 1e-6f);
    }
    __shared__ int is_last;
    if (t == 0) {
        __threadfence();
        int c = atomicAdd(&g_ctr, 1);
        is_last = (c == gridDim.x - 1) ? 1 : 0;
    }
    __syncthreads();
    if (!is_last) return;

    float best = -3.0e38f; int bidx = 0x7fffffff;
    for (int i = t; i < N; i += 128) {
        float v = g_sims[i];
        if (v > best) { best = v; bidx = i; }
    }
#pragma unroll
    for (int o = 16; o > 0; o >>= 1) {
        float ov = __shfl_xor_sync(0xffffffffu, best, o);
        int   oi = __shfl_xor_sync(0xffffffffu, bidx, o);
        if (ov > best || (ov == best && oi < bidx)) { best = ov; bidx = oi; }
    }
    __shared__ float svv[4]; __shared__ int sii[4];
    if (lane == 0) { svv[w] = best; sii[w] = bidx; }
    __syncthreads();
    if (t == 0) {
        float bv = svv[0]; int bi = sii[0];
#pragma unroll
        for (int i = 1; i < 4; i++) {
            if (svv[i] > bv || (svv[i] == bv && sii[i] < bi)) { bv = svv[i]; bi = sii[i]; }
        }
        float sim_val = fminf(fmaxf(bv, 0.0f), 1.0f);
        float kb = fminf(fmaxf(expf(p_lkb[0]), 0.01f), 4.0f);
        float kd = fminf(fmaxf(expf(p_lkd[0]), 0.01f), 0.9f);
        float fl = facil[bi] * ((sim_val > 0.88f) ? 2.0f : 1.0f);
        float mod = (fl - 1.0f) * sim_val;
        float boost = 1.0f + kb * mod;
        float damp = fmaxf(0.01f, 1.0f - kd * mod);
        g_nidx = bi;
        if (g_valid[bi]) { g_damp = damp; g_qscale = (boost - damp) / damp; }
        else             { g_damp = 1.0f; g_qscale = 0.0f; }
        g_ctr = 0;
    }
}

// ---------------- pass 2: warp-pair per row -----------------------------
// yd = gelu(x)*(0.5*ga*damp); proj over row via 2-warp pair; out = fmaf(q,v,yd)
__global__ void __launch_bounds__(BLK, 5) k_pass2(
    const float* __restrict__ x, const float* __restrict__ buf,
    float* __restrict__ out, int M)
{
    __shared__ float4 s_v[D_ / 4];
    __shared__ float s_p[2][PAIRS][2];   // [parity][pair][half]
    const int t = threadIdx.x;
    const int lane = t & 31, w = t >> 5;
    const int pair = w >> 1, half = w & 1;
    const float damp = g_damp;
    const float qscale = g_qscale;
    const int ni = g_nidx;

    {
        const float4* vp = (const float4*)(buf + (size_t)ni * D_);
        for (int i = t; i < D_ / 4; i += BLK) s_v[i] = vp[i];
    }
    __syncthreads();

    const int voff = half * 128 + lane;
    int parity = 0;
    for (int row = blockIdx.x * PAIRS + pair; row < M;
         row += GRIDP * PAIRS, parity ^= 1) {
        const float4* xp = (const float4*)(x + (size_t)row * D_) + voff;
        const float gad = 0.5f * damp * g_gate[row];
        float4 Y[4];
        float proj = 0.f;
#pragma unroll
        for (int k = 0; k < 4; k++) {
            float4 X = __ldcs(xp + 32 * k);
            float4 V = s_v[voff + 32 * k];
            float4 yy;
            float u0 = 0.7978845608028654f * fmaf(0.044715f * X.x, X.x * X.x, X.x);
            float u1 = 0.7978845608028654f * fmaf(0.044715f * X.y, X.y * X.y, X.y);
            float u2 = 0.7978845608028654f * fmaf(0.044715f * X.z, X.z * X.z, X.z);
            float u3 = 0.7978845608028654f * fmaf(0.044715f * X.w, X.w * X.w, X.w);
            yy.x = (X.x * gad) * (1.0f + tanh_ap(u0));
            yy.y = (X.y * gad) * (1.0f + tanh_ap(u1));
            yy.z = (X.z * gad) * (1.0f + tanh_ap(u2));
            yy.w = (X.w * gad) * (1.0f + tanh_ap(u3));
            Y[k] = yy;
            proj = fmaf(yy.x, V.x, fmaf(yy.y, V.y, fmaf(yy.z, V.z, fmaf(yy.w, V.w, proj))));
        }
        proj = wsum(proj);
        if (lane == 0) s_p[parity][pair][half] = proj;
        asm volatile("bar.sync %0, %1;" :: "r"(pair + 1), "r"(64) : "memory");
        const float q = (s_p[parity][pair][0] + s_p[parity][pair][1]) * qscale;
        float4* op = (float4*)(out + (size_t)row * D_) + voff;
#pragma unroll
        for (int k = 0; k < 4; k++) {
            float4 V = s_v[voff + 32 * k];
            float4 O;
            O.x = fmaf(q, V.x, Y[k].x);
            O.y = fmaf(q, V.y, Y[k].y);
            O.z = fmaf(q, V.z, Y[k].z);
            O.w = fmaf(q, V.w, Y[k].w);
            __stcs(op + 32 * k, O);
        }
        // double-buffered s_p: next write goes to other parity slot
    }
}

extern "C" void kernel_launch(void* const* d_in, const int* in_sizes, int n_in,
                              void* d_out, int out_size)
{
    const float* x      = (const float*)d_in[0];
    const float* lt_in  = (const float*)d_in[1];
    const float* lt_out = (const float*)d_in[2];
    const float* la_in  = (const float*)d_in[3];
    const float* la_out = (const float*)d_in[4];
    const float* lkb    = (const float*)d_in[5];
    const float* lkd    = (const float*)d_in[6];
    const float* ema_x  = (const float*)d_in[7];
    const float* ema_x2 = (const float*)d_in[8];
    const float* ema_y  = (const float*)d_in[9];
    const float* ema_y2 = (const float*)d_in[10];
    const float* buf    = (const float*)d_in[11];
    const float* facil  = (const float*)d_in[12];

    const int M = in_sizes[0] / D_;   // 16384
    const int N = in_sizes[11] / D_;  // 512
    float* out = (float*)d_out;

    k_pass1<<<GRIDP, BLK>>>(x, ema_x, ema_x2, ema_y, ema_y2,
                            lt_in, lt_out, la_in, la_out, M);
    k_colreduce<<<D_ / 8, BLK>>>(1.0f / (float)M);
    k_sims<<<N, 128>>>(buf, facil, lkb, lkd, N);
    k_pass2<<<GRIDP, BLK>>>(x, buf, out, M);
}

// round 6
// speedup vs baseline: 1.0172x; 1.0172x over previous
#include <cuda_runtime.h>
#include <math.h>

#define D_     1024
#define BLK    256
#define GRIDP  512
#define ROWS_  8
#define PAIRS  4
#define NMAX   512
#define MMAX   16384
#define EPS_   1e-5f

// ---- scratch (static device globals; no allocation) ----
__device__ float g_colpart[GRIDP * D_];
__device__ float g_gate[MMAX];
__device__ float g_mean[D_];
__device__ float g_sims[NMAX];
__device__ int   g_valid[NMAX];
__device__ float g_damp, g_qscale;   // qscale = coeff/damp
__device__ int   g_nidx;
__device__ int   g_ctr = 0;

__device__ __forceinline__ float wsum(float v) {
    v += __shfl_xor_sync(0xffffffffu, v, 16);
    v += __shfl_xor_sync(0xffffffffu, v, 8);
    v += __shfl_xor_sync(0xffffffffu, v, 4);
    v += __shfl_xor_sync(0xffffffffu, v, 2);
    v += __shfl_xor_sync(0xffffffffu, v, 1);
    return v;
}

// pairwise butterfly step: returns, at lanes with (lane&m)==0, partials of a;
// at lanes with bit set, partials of b. After all masks consumed, sums complete.
__device__ __forceinline__ float bfly(float a, float b, int lane, int m) {
    float sent = (lane & m) ? a : b;
    float recv = __shfl_xor_sync(0xffffffffu, sent, m);
    return ((lane & m) ? b : a) + recv;
}

__device__ __forceinline__ float tanh_ap(float u) {
    float r;
    asm("tanh.approx.f32 %0, %1;" : "=f"(r) : "f"(u));
    return r;
}

__device__ __forceinline__ float gelu_f(float x) {
    float u = 0.7978845608028654f * fmaf(0.044715f * x, x * x, x);
    return (0.5f * x) * (1.0f + tanh_ap(u));
}

// ---------------- pass 1: gates + y1 column partial sums ----------------
// one __syncthreads per 8-row chunk; butterfly z-reduce; 1 MUFU exp per lane
__global__ void __launch_bounds__(BLK) k_pass1(
    const float* __restrict__ x,
    const float* __restrict__ ema_x, const float* __restrict__ ema_x2,
    const float* __restrict__ ema_y, const float* __restrict__ ema_y2,
    const float* __restrict__ p_lt_in, const float* __restrict__ p_lt_out,
    const float* __restrict__ p_la_in, const float* __restrict__ p_la_out,
    int M)
{
    const int t = threadIdx.x;
    const int c = t * 4;
    const int lane = t & 31, w = t >> 5;

    float4 ex = *(const float4*)(ema_x + c);
    float4 e2 = *(const float4*)(ema_x2 + c);
    float4 ey = *(const float4*)(ema_y + c);
    float4 f2 = *(const float4*)(ema_y2 + c);
    float4 isx, isy, nx, ny;
    isx.x = 1.0f / (sqrtf(fmaxf(e2.x - ex.x * ex.x, 0.0f)) + EPS_);
    isx.y = 1.0f / (sqrtf(fmaxf(e2.y - ex.y * ex.y, 0.0f)) + EPS_);
    isx.z = 1.0f / (sqrtf(fmaxf(e2.z - ex.z * ex.z, 0.0f)) + EPS_);
    isx.w = 1.0f / (sqrtf(fmaxf(e2.w - ex.w * ex.w, 0.0f)) + EPS_);
    isy.x = 1.0f / (sqrtf(fmaxf(f2.x - ey.x * ey.x, 0.0f)) + EPS_);
    isy.y = 1.0f / (sqrtf(fmaxf(f2.y - ey.y * ey.y, 0.0f)) + EPS_);
    isy.z = 1.0f / (sqrtf(fmaxf(f2.z - ey.z * ey.z, 0.0f)) + EPS_);
    isy.w = 1.0f / (sqrtf(fmaxf(f2.w - ey.w * ey.w, 0.0f)) + EPS_);
    nx.x = -ex.x * isx.x; nx.y = -ex.y * isx.y; nx.z = -ex.z * isx.z; nx.w = -ex.w * isx.w;
    ny.x = -ey.x * isy.x; ny.y = -ey.y * isy.y; ny.z = -ey.z * isy.z; ny.w = -ey.w * isy.w;

    const float tau_in  = expf(p_lt_in[0]);
    const float tau_out = expf(p_lt_out[0]);
    const float a_in    = 1.0f / (1.0f + expf(-p_la_in[0]));
    const float a_out   = 1.0f / (1.0f + expf(-p_la_out[0]));
    // lane-selected params for the fused gin/gout evaluation
    const int li = lane & 15;
    const bool isin = (li < 8);
    const float tau_l = isin ? tau_in : tau_out;
    const float a_l   = isin ? a_in : a_out;
    const float b_l   = 1.0f - a_l;

    __shared__ float s_red[2][8][16];   // [parity][warp][zx0..7, zy0..7]

    float4 acc = make_float4(0.f, 0.f, 0.f, 0.f);
    const int nchunk = M / ROWS_;
    int parity = 0;

    for (int ch = blockIdx.x; ch < nchunk; ch += GRIDP, parity ^= 1) {
        const float* xp = x + (size_t)ch * (ROWS_ * D_) + c;
        float4 xv[ROWS_];
#pragma unroll
        for (int r = 0; r < ROWS_; r++)
            xv[r] = *(const float4*)(xp + r * D_);

        float4 yv[ROWS_];
        float zx[ROWS_], zy[ROWS_];
#pragma unroll
        for (int r = 0; r < ROWS_; r++) {
            float4 X = xv[r];
            float4 Y;
            Y.x = gelu_f(X.x); Y.y = gelu_f(X.y);
            Y.z = gelu_f(X.z); Y.w = gelu_f(X.w);
            yv[r] = Y;
            float d0 = fmaf(X.x, isx.x, nx.x), d1 = fmaf(X.y, isx.y, nx.y);
            float d2 = fmaf(X.z, isx.z, nx.z), d3 = fmaf(X.w, isx.w, nx.w);
            zx[r] = fmaf(d0, d0, fmaf(d1, d1, fmaf(d2, d2, d3 * d3)));
            float g0 = fmaf(Y.x, isy.x, ny.x), g1 = fmaf(Y.y, isy.y, ny.y);
            float g2 = fmaf(Y.z, isy.z, ny.z), g3 = fmaf(Y.w, isy.w, ny.w);
            zy[r] = fmaf(g0, g0, fmaf(g1, g1, fmaf(g2, g2, g3 * g3)));
        }

        // 16-value butterfly: result at lane -> row=(b8<<2|b4<<1|b2), type=b16
        float v[8];
#pragma unroll
        for (int r = 0; r < 8; r++) v[r] = bfly(zx[r], zy[r], lane, 16);
        float u0 = bfly(v[0], v[4], lane, 8);
        float u1 = bfly(v[1], v[5], lane, 8);
        float u2 = bfly(v[2], v[6], lane, 8);
        float u3 = bfly(v[3], v[7], lane, 8);
        float s0 = bfly(u0, u2, lane, 4);
        float s1 = bfly(u1, u3, lane, 4);
        float z  = bfly(s0, s1, lane, 2);
        z += __shfl_xor_sync(0xffffffffu, z, 1);

        if ((lane & 1) == 0) {
            int idx = ((lane & 14) >> 1) | ((lane & 16) >> 1);  // 0..7 zx, 8..15 zy
            s_red[parity][w][idx] = z;
        }
        __syncthreads();

        // each warp: lane li holds z for (row = li&7, type = li>>3)
        float zsum = 0.f;
#pragma unroll
        for (int ww = 0; ww < 8; ww++) zsum += s_red[parity][ww][li];
        zsum *= (1.0f / D_);
        float f = fmaf(a_l, __expf(-tau_l * zsum), b_l);      // gin (li<8) or gout
        float fo = __shfl_sync(0xffffffffu, f, (lane & 7) + 8); // gout for row lane&7
        float g = f * fo;                                       // valid at lanes 0..7
        if (w == 0 && lane < 8) g_gate[ch * ROWS_ + lane] = g;
#pragma unroll
        for (int r = 0; r < ROWS_; r++) {
            float ga = __shfl_sync(0xffffffffu, g, r);
            acc.x = fmaf(yv[r].x, ga, acc.x);
            acc.y = fmaf(yv[r].y, ga, acc.y);
            acc.z = fmaf(yv[r].z, ga, acc.z);
            acc.w = fmaf(yv[r].w, ga, acc.w);
        }
        // double-buffered s_red: no trailing barrier needed
    }
    *(float4*)(g_colpart + blockIdx.x * D_ + c) = acc;
}

// ---------------- reduce column partials -> y1_mean ---------------------
__global__ void __launch_bounds__(BLK) k_colreduce(float invM)
{
    const int t = threadIdx.x;
    const int col = blockIdx.x * 8 + (t & 7);
    const int gs = t >> 3;
    float s = 0.f;
#pragma unroll
    for (int k = 0; k < GRIDP / 32; k++) {
        int g = gs + k * 32;
        s += g_colpart[g * D_ + col];
    }
    __shared__ float sm[32][8];
    sm[gs][t & 7] = s;
    __syncthreads();
    if (t < 8) {
        float tot = 0.f;
#pragma unroll
        for (int i = 0; i < 32; i++) tot += sm[i][t];
        g_mean[blockIdx.x * 8 + t] = tot * invM;
    }
}

// ---------------- sims + fused argmax/select ----------------------------
__global__ void __launch_bounds__(128) k_sims(
    const float* __restrict__ buf, const float* __restrict__ facil,
    const float* __restrict__ p_lkb, const float* __restrict__ p_lkd,
    int N)
{
    const int n = blockIdx.x;
    const int t = threadIdx.x;
    const int lane = t & 31, w = t >> 5;
    const float4* bp = (const float4*)(buf + (size_t)n * D_);
    const float4* mp = (const float4*)g_mean;

    float dot = 0.f, b2 = 0.f, m2 = 0.f;
    int fin = 1;
#pragma unroll
    for (int k = 0; k < 2; k++) {
        float4 bv = bp[t + k * 128];
        float4 mv = mp[t + k * 128];
        dot = fmaf(bv.x, mv.x, fmaf(bv.y, mv.y, fmaf(bv.z, mv.z, fmaf(bv.w, mv.w, dot))));
        b2  = fmaf(bv.x, bv.x, fmaf(bv.y, bv.y, fmaf(bv.z, bv.z, fmaf(bv.w, bv.w, b2))));
        m2  = fmaf(mv.x, mv.x, fmaf(mv.y, mv.y, fmaf(mv.z, mv.z, fmaf(mv.w, mv.w, m2))));
        fin &= (fabsf(bv.x) <= 3.4028234e38f) & (fabsf(bv.y) <= 3.4028234e38f) &
               (fabsf(bv.z) <= 3.4028234e38f) & (fabsf(bv.w) <= 3.4028234e38f);
    }
    dot = wsum(dot); b2 = wsum(b2); m2 = wsum(m2);
    fin = __all_sync(0xffffffffu, fin);
    __shared__ float sd[4], sb[4], sm2[4];
    __shared__ int sf[4];
    if (lane == 0) { sd[w] = dot; sb[w] = b2; sm2[w] = m2; sf[w] = fin; }
    __syncthreads();
    if (t == 0) {
        float dt = sd[0] + sd[1] + sd[2] + sd[3];
        float bb = sb[0] + sb[1] + sb[2] + sb[3];
        float mm = sm2[0] + sm2[1] + sm2[2] + sm2[3];
        float bnorm = fmaxf(sqrtf(bb), 1e-12f);
        float mnorm = fmaxf(sqrtf(mm), 1e-12f);
        g_sims[n] = dt / (bnorm * mnorm);
        g_valid[n] = (sf[0] & sf[1] & sf[2] & sf[3]) && (sqrtf(bb) >= 1e-6f);
    }
    __shared__ int is_last;
    if (t == 0) {
        __threadfence();
        int c = atomicAdd(&g_ctr, 1);
        is_last = (c == gridDim.x - 1) ? 1 : 0;
    }
    __syncthreads();
    if (!is_last) return;

    float best = -3.0e38f; int bidx = 0x7fffffff;
    for (int i = t; i < N; i += 128) {
        float v = g_sims[i];
        if (v > best) { best = v; bidx = i; }
    }
#pragma unroll
    for (int o = 16; o > 0; o >>= 1) {
        float ov = __shfl_xor_sync(0xffffffffu, best, o);
        int   oi = __shfl_xor_sync(0xffffffffu, bidx, o);
        if (ov > best || (ov == best && oi < bidx)) { best = ov; bidx = oi; }
    }
    __shared__ float svv[4]; __shared__ int sii[4];
    if (lane == 0) { svv[w] = best; sii[w] = bidx; }
    __syncthreads();
    if (t == 0) {
        float bv = svv[0]; int bi = sii[0];
#pragma unroll
        for (int i = 1; i < 4; i++) {
            if (svv[i] > bv || (svv[i] == bv && sii[i] < bi)) { bv = svv[i]; bi = sii[i]; }
        }
        float sim_val = fminf(fmaxf(bv, 0.0f), 1.0f);
        float kb = fminf(fmaxf(expf(p_lkb[0]), 0.01f), 4.0f);
        float kd = fminf(fmaxf(expf(p_lkd[0]), 0.01f), 0.9f);
        float fl = facil[bi] * ((sim_val > 0.88f) ? 2.0f : 1.0f);
        float mod = (fl - 1.0f) * sim_val;
        float boost = 1.0f + kb * mod;
        float damp = fmaxf(0.01f, 1.0f - kd * mod);
        g_nidx = bi;
        if (g_valid[bi]) { g_damp = damp; g_qscale = (boost - damp) / damp; }
        else             { g_damp = 1.0f; g_qscale = 0.0f; }
        g_ctr = 0;
    }
}

// ---------------- pass 2: warp-pair per row -----------------------------
__global__ void __launch_bounds__(BLK, 5) k_pass2(
    const float* __restrict__ x, const float* __restrict__ buf,
    float* __restrict__ out, int M)
{
    __shared__ float4 s_v[D_ / 4];
    __shared__ float s_p[2][PAIRS][2];
    const int t = threadIdx.x;
    const int lane = t & 31, w = t >> 5;
    const int pair = w >> 1, half = w & 1;
    const float damp = g_damp;
    const float qscale = g_qscale;
    const int ni = g_nidx;

    {
        const float4* vp = (const float4*)(buf + (size_t)ni * D_);
        for (int i = t; i < D_ / 4; i += BLK) s_v[i] = vp[i];
    }
    __syncthreads();

    const int voff = half * 128 + lane;
    int parity = 0;
    for (int row = blockIdx.x * PAIRS + pair; row < M;
         row += GRIDP * PAIRS, parity ^= 1) {
        const float4* xp = (const float4*)(x + (size_t)row * D_) + voff;
        const float gad = 0.5f * damp * g_gate[row];
        float4 Y[4];
        float proj = 0.f;
#pragma unroll
        for (int k = 0; k < 4; k++) {
            float4 X = __ldcs(xp + 32 * k);
            float4 V = s_v[voff + 32 * k];
            float4 yy;
            float u0 = 0.7978845608028654f * fmaf(0.044715f * X.x, X.x * X.x, X.x);
            float u1 = 0.7978845608028654f * fmaf(0.044715f * X.y, X.y * X.y, X.y);
            float u2 = 0.7978845608028654f * fmaf(0.044715f * X.z, X.z * X.z, X.z);
            float u3 = 0.7978845608028654f * fmaf(0.044715f * X.w, X.w * X.w, X.w);
            yy.x = (X.x * gad) * (1.0f + tanh_ap(u0));
            yy.y = (X.y * gad) * (1.0f + tanh_ap(u1));
            yy.z = (X.z * gad) * (1.0f + tanh_ap(u2));
            yy.w = (X.w * gad) * (1.0f + tanh_ap(u3));
            Y[k] = yy;
            proj = fmaf(yy.x, V.x, fmaf(yy.y, V.y, fmaf(yy.z, V.z, fmaf(yy.w, V.w, proj))));
        }
        proj = wsum(proj);
        if (lane == 0) s_p[parity][pair][half] = proj;
        asm volatile("bar.sync %0, %1;" :: "r"(pair + 1), "r"(64) : "memory");
        const float q = (s_p[parity][pair][0] + s_p[parity][pair][1]) * qscale;
        float4* op = (float4*)(out + (size_t)row * D_) + voff;
#pragma unroll
        for (int k = 0; k < 4; k++) {
            float4 V = s_v[voff + 32 * k];
            float4 O;
            O.x = fmaf(q, V.x, Y[k].x);
            O.y = fmaf(q, V.y, Y[k].y);
            O.z = fmaf(q, V.z, Y[k].z);
            O.w = fmaf(q, V.w, Y[k].w);
            __stcs(op + 32 * k, O);
        }
    }
}

extern "C" void kernel_launch(void* const* d_in, const int* in_sizes, int n_in,
                              void* d_out, int out_size)
{
    const float* x      = (const float*)d_in[0];
    const float* lt_in  = (const float*)d_in[1];
    const float* lt_out = (const float*)d_in[2];
    const float* la_in  = (const float*)d_in[3];
    const float* la_out = (const float*)d_in[4];
    const float* lkb    = (const float*)d_in[5];
    const float* lkd    = (const float*)d_in[6];
    const float* ema_x  = (const float*)d_in[7];
    const float* ema_x2 = (const float*)d_in[8];
    const float* ema_y  = (const float*)d_in[9];
    const float* ema_y2 = (const float*)d_in[10];
    const float* buf    = (const float*)d_in[11];
    const float* facil  = (const float*)d_in[12];

    const int M = in_sizes[0] / D_;   // 16384
    const int N = in_sizes[11] / D_;  // 512
    float* out = (float*)d_out;

    k_pass1<<<GRIDP, BLK>>>(x, ema_x, ema_x2, ema_y, ema_y2,
                            lt_in, lt_out, la_in, la_out, M);
    k_colreduce<<<D_ / 8, BLK>>>(1.0f / (float)M);
    k_sims<<<N, 128>>>(buf, facil, lkb, lkd, N);
    k_pass2<<<GRIDP, BLK>>>(x, buf, out, M);
}

// round 7
// speedup vs baseline: 1.0664x; 1.0483x over previous
#include <cuda_runtime.h>
#include <math.h>

#define D_     1024
#define BLK    256
#define GRIDP  512        // pass1 blocks (2048 chunks / 512 = 4 iters exactly)
#define GRIDP2 740        // pass2 blocks = 5 CTA/SM * 148 SMs
#define ROWS_  8
#define PAIRS  4
#define NMAX   512
#define MMAX   16384
#define EPS_   1e-5f

// ---- scratch (static device globals; no allocation) ----
__device__ float g_colpart[GRIDP * D_];
__device__ float g_gate[MMAX];
__device__ float g_mean[D_];
__device__ float g_sims[NMAX];
__device__ int   g_valid[NMAX];
__device__ float g_damp, g_qscale;
__device__ int   g_nidx;
__device__ int   g_ctr = 0;    // select arrival counter
__device__ int   g_ctr2 = 0;   // colreduce arrival counter

__device__ __forceinline__ float wsum(float v) {
    v += __shfl_xor_sync(0xffffffffu, v, 16);
    v += __shfl_xor_sync(0xffffffffu, v, 8);
    v += __shfl_xor_sync(0xffffffffu, v, 4);
    v += __shfl_xor_sync(0xffffffffu, v, 2);
    v += __shfl_xor_sync(0xffffffffu, v, 1);
    return v;
}

__device__ __forceinline__ float bfly(float a, float b, int lane, int m) {
    float sent = (lane & m) ? a : b;
    float recv = __shfl_xor_sync(0xffffffffu, sent, m);
    return ((lane & m) ? b : a) + recv;
}

__device__ __forceinline__ float tanh_ap(float u) {
    float r;
    asm("tanh.approx.f32 %0, %1;" : "=f"(r) : "f"(u));
    return r;
}

__device__ __forceinline__ float gelu_f(float x) {
    float u = 0.7978845608028654f * fmaf(0.044715f * x, x * x, x);
    return (0.5f * x) * (1.0f + tanh_ap(u));
}

// ---------------- pass 1: gates + y1 column partial sums ----------------
__global__ void __launch_bounds__(BLK, 4) k_pass1(
    const float* __restrict__ x,
    const float* __restrict__ ema_x, const float* __restrict__ ema_x2,
    const float* __restrict__ ema_y, const float* __restrict__ ema_y2,
    const float* __restrict__ p_lt_in, const float* __restrict__ p_lt_out,
    const float* __restrict__ p_la_in, const float* __restrict__ p_la_out,
    int M)
{
    const int t = threadIdx.x;
    const int c = t * 4;
    const int lane = t & 31, w = t >> 5;

    float4 ex = *(const float4*)(ema_x + c);
    float4 e2 = *(const float4*)(ema_x2 + c);
    float4 ey = *(const float4*)(ema_y + c);
    float4 f2 = *(const float4*)(ema_y2 + c);
    float4 isx, isy, nx, ny;
    isx.x = 1.0f / (sqrtf(fmaxf(e2.x - ex.x * ex.x, 0.0f)) + EPS_);
    isx.y = 1.0f / (sqrtf(fmaxf(e2.y - ex.y * ex.y, 0.0f)) + EPS_);
    isx.z = 1.0f / (sqrtf(fmaxf(e2.z - ex.z * ex.z, 0.0f)) + EPS_);
    isx.w = 1.0f / (sqrtf(fmaxf(e2.w - ex.w * ex.w, 0.0f)) + EPS_);
    isy.x = 1.0f / (sqrtf(fmaxf(f2.x - ey.x * ey.x, 0.0f)) + EPS_);
    isy.y = 1.0f / (sqrtf(fmaxf(f2.y - ey.y * ey.y, 0.0f)) + EPS_);
    isy.z = 1.0f / (sqrtf(fmaxf(f2.z - ey.z * ey.z, 0.0f)) + EPS_);
    isy.w = 1.0f / (sqrtf(fmaxf(f2.w - ey.w * ey.w, 0.0f)) + EPS_);
    nx.x = -ex.x * isx.x; nx.y = -ex.y * isx.y; nx.z = -ex.z * isx.z; nx.w = -ex.w * isx.w;
    ny.x = -ey.x * isy.x; ny.y = -ey.y * isy.y; ny.z = -ey.z * isy.z; ny.w = -ey.w * isy.w;

    const float tau_in  = expf(p_lt_in[0]);
    const float tau_out = expf(p_lt_out[0]);
    const float a_in    = 1.0f / (1.0f + expf(-p_la_in[0]));
    const float a_out   = 1.0f / (1.0f + expf(-p_la_out[0]));
    const int li = lane & 15;
    const bool isin = (li < 8);
    const float tau_l = isin ? tau_in : tau_out;
    const float a_l   = isin ? a_in : a_out;
    const float b_l   = 1.0f - a_l;

    __shared__ float s_red[2][8][16];

    float4 acc = make_float4(0.f, 0.f, 0.f, 0.f);
    const int nchunk = M / ROWS_;
    int parity = 0;

    for (int ch = blockIdx.x; ch < nchunk; ch += GRIDP, parity ^= 1) {
        const float* xp = x + (size_t)ch * (ROWS_ * D_) + c;
        float4 xv[ROWS_];
#pragma unroll
        for (int r = 0; r < ROWS_; r++)
            xv[r] = *(const float4*)(xp + r * D_);

        float4 yv[ROWS_];
        float zx[ROWS_], zy[ROWS_];
#pragma unroll
        for (int r = 0; r < ROWS_; r++) {
            float4 X = xv[r];
            float4 Y;
            Y.x = gelu_f(X.x); Y.y = gelu_f(X.y);
            Y.z = gelu_f(X.z); Y.w = gelu_f(X.w);
            yv[r] = Y;
            float d0 = fmaf(X.x, isx.x, nx.x), d1 = fmaf(X.y, isx.y, nx.y);
            float d2 = fmaf(X.z, isx.z, nx.z), d3 = fmaf(X.w, isx.w, nx.w);
            zx[r] = fmaf(d0, d0, fmaf(d1, d1, fmaf(d2, d2, d3 * d3)));
            float g0 = fmaf(Y.x, isy.x, ny.x), g1 = fmaf(Y.y, isy.y, ny.y);
            float g2 = fmaf(Y.z, isy.z, ny.z), g3 = fmaf(Y.w, isy.w, ny.w);
            zy[r] = fmaf(g0, g0, fmaf(g1, g1, fmaf(g2, g2, g3 * g3)));
        }

        float v[8];
#pragma unroll
        for (int r = 0; r < 8; r++) v[r] = bfly(zx[r], zy[r], lane, 16);
        float u0 = bfly(v[0], v[4], lane, 8);
        float u1 = bfly(v[1], v[5], lane, 8);
        float u2 = bfly(v[2], v[6], lane, 8);
        float u3 = bfly(v[3], v[7], lane, 8);
        float s0 = bfly(u0, u2, lane, 4);
        float s1 = bfly(u1, u3, lane, 4);
        float z  = bfly(s0, s1, lane, 2);
        z += __shfl_xor_sync(0xffffffffu, z, 1);

        if ((lane & 1) == 0) {
            int idx = ((lane & 14) >> 1) | ((lane & 16) >> 1);
            s_red[parity][w][idx] = z;
        }
        __syncthreads();

        float zsum = 0.f;
#pragma unroll
        for (int ww = 0; ww < 8; ww++) zsum += s_red[parity][ww][li];
        zsum *= (1.0f / D_);
        float f = fmaf(a_l, __expf(-tau_l * zsum), b_l);
        float fo = __shfl_sync(0xffffffffu, f, (lane & 7) + 8);
        float g = f * fo;
        if (w == 0 && lane < 8) g_gate[ch * ROWS_ + lane] = g;
#pragma unroll
        for (int r = 0; r < ROWS_; r++) {
            float ga = __shfl_sync(0xffffffffu, g, r);
            acc.x = fmaf(yv[r].x, ga, acc.x);
            acc.y = fmaf(yv[r].y, ga, acc.y);
            acc.z = fmaf(yv[r].z, ga, acc.z);
            acc.w = fmaf(yv[r].w, ga, acc.w);
        }
    }
    *(float4*)(g_colpart + blockIdx.x * D_ + c) = acc;
}

// ------------- fused colreduce + sims + select (512 x 128) --------------
// All 512 blocks (128 thr) are simultaneously resident (>=10 CTA/SM cap),
// so an arrival-counter spin between phases cannot deadlock.
__global__ void __launch_bounds__(128) k_mid(
    const float* __restrict__ buf, const float* __restrict__ facil,
    const float* __restrict__ p_lkb, const float* __restrict__ p_lkd,
    int N, float invM)
{
    const int n = blockIdx.x;
    const int t = threadIdx.x;
    const int lane = t & 31, w = t >> 5;

    // ---- phase A: blocks 0..127 reduce 8 columns each ----
    if (n < 128) {
        const int col = n * 8 + (t & 7);
        const int gs = t >> 3;                 // 0..15
        float s = 0.f;
#pragma unroll
        for (int k = 0; k < GRIDP / 16; k++)   // 32 slices per thread
            s += g_colpart[(gs + k * 16) * D_ + col];
        __shared__ float sm[16][8];
        sm[gs][t & 7] = s;
        __syncthreads();
        if (t < 8) {
            float tot = 0.f;
#pragma unroll
            for (int i = 0; i < 16; i++) tot += sm[i][t];
            g_mean[n * 8 + t] = tot * invM;
        }
        if (t == 0) { __threadfence(); atomicAdd(&g_ctr2, 1); }
    }
    // ---- wait for all means ----
    if (t == 0) {
        while (atomicAdd(&g_ctr2, 0) < 128) { }
    }
    __syncthreads();

    // ---- phase B: sims[n] ----
    const float4* bp = (const float4*)(buf + (size_t)n * D_);
    const float4* mp = (const float4*)g_mean;
    float dot = 0.f, b2 = 0.f, m2 = 0.f;
    int fin = 1;
#pragma unroll
    for (int k = 0; k < 2; k++) {
        float4 bv = bp[t + k * 128];
        float4 mv = mp[t + k * 128];
        dot = fmaf(bv.x, mv.x, fmaf(bv.y, mv.y, fmaf(bv.z, mv.z, fmaf(bv.w, mv.w, dot))));
        b2  = fmaf(bv.x, bv.x, fmaf(bv.y, bv.y, fmaf(bv.z, bv.z, fmaf(bv.w, bv.w, b2))));
        m2  = fmaf(mv.x, mv.x, fmaf(mv.y, mv.y, fmaf(mv.z, mv.z, fmaf(mv.w, mv.w, m2))));
        fin &= (fabsf(bv.x) <= 3.4028234e38f) & (fabsf(bv.y) <= 3.4028234e38f) &
               (fabsf(bv.z) <= 3.4028234e38f) & (fabsf(bv.w) <= 3.4028234e38f);
    }
    dot = wsum(dot); b2 = wsum(b2); m2 = wsum(m2);
    fin = __all_sync(0xffffffffu, fin);
    __shared__ float sd[4], sb[4], sm2[4];
    __shared__ int sf[4];
    if (lane == 0) { sd[w] = dot; sb[w] = b2; sm2[w] = m2; sf[w] = fin; }
    __syncthreads();
    if (t == 0) {
        float dt = sd[0] + sd[1] + sd[2] + sd[3];
        float bb = sb[0] + sb[1] + sb[2] + sb[3];
        float mm = sm2[0] + sm2[1] + sm2[2] + sm2[3];
        float bnorm = fmaxf(sqrtf(bb), 1e-12f);
        float mnorm = fmaxf(sqrtf(mm), 1e-12f);
        g_sims[n] = dt / (bnorm * mnorm);
        g_valid[n] = (sf[0] & sf[1] & sf[2] & sf[3]) && (sqrtf(bb) >= 1e-6f);
    }
    __shared__ int is_last;
    if (t == 0) {
        __threadfence();
        int c = atomicAdd(&g_ctr, 1);
        is_last = (c == gridDim.x - 1) ? 1 : 0;
    }
    __syncthreads();
    if (!is_last) return;

    // ---- phase C: argmax + scalars (last block only) ----
    float best = -3.0e38f; int bidx = 0x7fffffff;
    for (int i = t; i < N; i += 128) {
        float v = g_sims[i];
        if (v > best) { best = v; bidx = i; }
    }
#pragma unroll
    for (int o = 16; o > 0; o >>= 1) {
        float ov = __shfl_xor_sync(0xffffffffu, best, o);
        int   oi = __shfl_xor_sync(0xffffffffu, bidx, o);
        if (ov > best || (ov == best && oi < bidx)) { best = ov; bidx = oi; }
    }
    __shared__ float svv[4]; __shared__ int sii[4];
    if (lane == 0) { svv[w] = best; sii[w] = bidx; }
    __syncthreads();
    if (t == 0) {
        float bv = svv[0]; int bi = sii[0];
#pragma unroll
        for (int i = 1; i < 4; i++) {
            if (svv[i] > bv || (svv[i] == bv && sii[i] < bi)) { bv = svv[i]; bi = sii[i]; }
        }
        float sim_val = fminf(fmaxf(bv, 0.0f), 1.0f);
        float kb = fminf(fmaxf(expf(p_lkb[0]), 0.01f), 4.0f);
        float kd = fminf(fmaxf(expf(p_lkd[0]), 0.01f), 0.9f);
        float fl = facil[bi] * ((sim_val > 0.88f) ? 2.0f : 1.0f);
        float mod = (fl - 1.0f) * sim_val;
        float boost = 1.0f + kb * mod;
        float damp = fmaxf(0.01f, 1.0f - kd * mod);
        g_nidx = bi;
        if (g_valid[bi]) { g_damp = damp; g_qscale = (boost - damp) / damp; }
        else             { g_damp = 1.0f; g_qscale = 0.0f; }
        g_ctr = 0;
        g_ctr2 = 0;   // reset both for next graph replay
    }
}

// ---------------- pass 2: warp-pair per row -----------------------------
__global__ void __launch_bounds__(BLK, 5) k_pass2(
    const float* __restrict__ x, const float* __restrict__ buf,
    float* __restrict__ out, int M)
{
    __shared__ float4 s_v[D_ / 4];
    __shared__ float s_p[2][PAIRS][2];
    const int t = threadIdx.x;
    const int lane = t & 31, w = t >> 5;
    const int pair = w >> 1, half = w & 1;
    const float damp = g_damp;
    const float qscale = g_qscale;
    const int ni = g_nidx;

    {
        const float4* vp = (const float4*)(buf + (size_t)ni * D_);
        for (int i = t; i < D_ / 4; i += BLK) s_v[i] = vp[i];
    }
    __syncthreads();

    const int voff = half * 128 + lane;
    int parity = 0;
    for (int row = blockIdx.x * PAIRS + pair; row < M;
         row += GRIDP2 * PAIRS, parity ^= 1) {
        const float4* xp = (const float4*)(x + (size_t)row * D_) + voff;
        const float gad = 0.5f * damp * g_gate[row];
        float4 Y[4];
        float proj = 0.f;
#pragma unroll
        for (int k = 0; k < 4; k++) {
            float4 X = __ldcs(xp + 32 * k);
            float4 V = s_v[voff + 32 * k];
            float4 yy;
            float u0 = 0.7978845608028654f * fmaf(0.044715f * X.x, X.x * X.x, X.x);
            float u1 = 0.7978845608028654f * fmaf(0.044715f * X.y, X.y * X.y, X.y);
            float u2 = 0.7978845608028654f * fmaf(0.044715f * X.z, X.z * X.z, X.z);
            float u3 = 0.7978845608028654f * fmaf(0.044715f * X.w, X.w * X.w, X.w);
            yy.x = (X.x * gad) * (1.0f + tanh_ap(u0));
            yy.y = (X.y * gad) * (1.0f + tanh_ap(u1));
            yy.z = (X.z * gad) * (1.0f + tanh_ap(u2));
            yy.w = (X.w * gad) * (1.0f + tanh_ap(u3));
            Y[k] = yy;
            proj = fmaf(yy.x, V.x, fmaf(yy.y, V.y, fmaf(yy.z, V.z, fmaf(yy.w, V.w, proj))));
        }
        proj = wsum(proj);
        if (lane == 0) s_p[parity][pair][half] = proj;
        asm volatile("bar.sync %0, %1;" :: "r"(pair + 1), "r"(64) : "memory");
        const float q = (s_p[parity][pair][0] + s_p[parity][pair][1]) * qscale;
        float4* op = (float4*)(out + (size_t)row * D_) + voff;
#pragma unroll
        for (int k = 0; k < 4; k++) {
            float4 V = s_v[voff + 32 * k];
            float4 O;
            O.x = fmaf(q, V.x, Y[k].x);
            O.y = fmaf(q, V.y, Y[k].y);
            O.z = fmaf(q, V.z, Y[k].z);
            O.w = fmaf(q, V.w, Y[k].w);
            __stcs(op + 32 * k, O);
        }
    }
}

extern "C" void kernel_launch(void* const* d_in, const int* in_sizes, int n_in,
                              void* d_out, int out_size)
{
    const float* x      = (const float*)d_in[0];
    const float* lt_in  = (const float*)d_in[1];
    const float* lt_out = (const float*)d_in[2];
    const float* la_in  = (const float*)d_in[3];
    const float* la_out = (const float*)d_in[4];
    const float* lkb    = (const float*)d_in[5];
    const float* lkd    = (const float*)d_in[6];
    const float* ema_x  = (const float*)d_in[7];
    const float* ema_x2 = (const float*)d_in[8];
    const float* ema_y  = (const float*)d_in[9];
    const float* ema_y2 = (const float*)d_in[10];
    const float* buf    = (const float*)d_in[11];
    const float* facil  = (const float*)d_in[12];

    const int M = in_sizes[0] / D_;   // 16384
    const int N = in_sizes[11] / D_;  // 512
    float* out = (float*)d_out;

    k_pass1<<<GRIDP, BLK>>>(x, ema_x, ema_x2, ema_y, ema_y2,
                            lt_in, lt_out, la_in, la_out, M);
    k_mid<<<N, 128>>>(buf, facil, lkb, lkd, N, 1.0f / (float)M);
    k_pass2<<<GRIDP2, BLK>>>(x, buf, out, M);
}